// round 3
// baseline (speedup 1.0000x reference)
#include <cuda_runtime.h>
#include <math.h>

#define NN 4096
#define HH 64
#define G4 256
#define TT 48
#define MAXNZ 128
#define SZH (NN*HH)

// ---------------- device scratch (static, no allocation) ----------------
__device__ float g_dinv[NN];
__device__ int   g_cnt[NN];
__device__ int   g_cols[NN*MAXNZ];
__device__ float g_vals[NN*MAXNZ];
__device__ float g_Xall[NN*96];
__device__ float g_AX[NN*96];
__device__ float g_h0[2*SZH];
__device__ float g_h1[2*SZH];
__device__ float g_c0[SZH];
__device__ float g_c1[SZH];
__device__ float g_W0[128*G4];   // [gcWh0 ; liWh0]
__device__ float g_W1[256*G4];   // [gcWi1 ; liWi1 ; gcWh1 ; liWh1]
__device__ float g_b0[G4];
__device__ float g_b1[G4];
__device__ float g_WX[4*G4];     // [gcWi0 rows 0,1 ; liWi0 rows 0,1]

__device__ __forceinline__ float sigf(float x) { return 1.0f / (1.0f + expf(-x)); }

// ---------------- setup kernels ----------------

__global__ void deg_kernel(const float* __restrict__ adj) {
    __shared__ float red[256];
    const int r = blockIdx.x;
    float s = 0.0f;
    for (int c = threadIdx.x; c < NN; c += 256) s += adj[(long)r*NN + c];
    red[threadIdx.x] = s;
    __syncthreads();
    for (int o = 128; o > 0; o >>= 1) {
        if (threadIdx.x < o) red[threadIdx.x] += red[threadIdx.x + o];
        __syncthreads();
    }
    if (threadIdx.x == 0) g_dinv[r] = 1.0f / sqrtf(red[0] + 1.0f);
}

// Deterministic ELL build via ballot/popc compaction. val = (adj + I) * dinv_r * dinv_c.
__global__ void ell_kernel(const float* __restrict__ adj) {
    const int lane = threadIdx.x & 31;
    const int r = blockIdx.x * 8 + (threadIdx.x >> 5);
    const float dr = g_dinv[r];
    int base = 0;
    for (int c0 = 0; c0 < NN; c0 += 32) {
        const int c = c0 + lane;
        float a = adj[(long)r*NN + c];
        if (c == r) a += 1.0f;
        const unsigned m = __ballot_sync(0xffffffffu, a != 0.0f);
        if (a != 0.0f) {
            const int pos = base + __popc(m & ((1u << lane) - 1u));
            if (pos < MAXNZ) {
                g_cols[r*MAXNZ + pos] = c;
                g_vals[r*MAXNZ + pos] = a * dr * g_dinv[c];
            }
        }
        base += __popc(m);
    }
    if (lane == 0) g_cnt[r] = (base < MAXNZ) ? base : MAXNZ;
}

__global__ void xall_kernel(const float* __restrict__ x) {
    const int idx = blockIdx.x * 256 + threadIdx.x;   // < NN*96
    const int n = idx / 96;
    const int q = idx - n * 96;
    const int t = q >> 1, i = q & 1;
    g_Xall[idx] = x[t * (NN*2) + n*2 + i];
}

__global__ void spmm96_kernel() {
    const int lane = threadIdx.x & 31;
    const int r = blockIdx.x * 8 + (threadIdx.x >> 5);
    const int cn = g_cnt[r];
    const int*   cp = g_cols + r*MAXNZ;
    const float* vp = g_vals + r*MAXNZ;
    float a0 = 0.f, a1 = 0.f, a2 = 0.f;
    for (int k = 0; k < cn; k++) {
        const int c = cp[k]; const float v = vp[k];
        a0 += v * g_Xall[c*96 + lane];
        a1 += v * g_Xall[c*96 + lane + 32];
        a2 += v * g_Xall[c*96 + lane + 64];
    }
    g_AX[r*96 + lane]      = a0;
    g_AX[r*96 + lane + 32] = a1;
    g_AX[r*96 + lane + 64] = a2;
}

__global__ void setup_kernel(
    const float* __restrict__ gcWi0, const float* __restrict__ liWi0,
    const float* __restrict__ gcWh0, const float* __restrict__ liWh0,
    const float* __restrict__ gcWi1, const float* __restrict__ liWi1,
    const float* __restrict__ gcWh1, const float* __restrict__ liWh1,
    const float* __restrict__ gcbi0, const float* __restrict__ gcbh0,
    const float* __restrict__ libi0, const float* __restrict__ libh0,
    const float* __restrict__ gcbi1, const float* __restrict__ gcbh1,
    const float* __restrict__ libi1, const float* __restrict__ libh1)
{
    for (int idx = blockIdx.x*blockDim.x + threadIdx.x; idx < 65536;
         idx += gridDim.x*blockDim.x) {
        const int r = idx >> 8, c = idx & 255;
        const float* s1 = (r < 64) ? gcWi1 : (r < 128) ? liWi1 : (r < 192) ? gcWh1 : liWh1;
        g_W1[idx] = s1[(r & 63)*256 + c];
        if (r < 128) {
            const float* s0 = (r < 64) ? gcWh0 : liWh0;
            g_W0[idx] = s0[(r & 63)*256 + c];
        }
        if (r < 4)
            g_WX[idx] = (r < 2) ? gcWi0[r*256 + c] : liWi0[(r - 2)*256 + c];
        if (r == 0) {
            g_b0[c] = gcbi0[c] + gcbh0[c] + libi0[c] + libh0[c];
            g_b1[c] = gcbi1[c] + gcbh1[c] + libi1[c] + libh1[c];
        }
    }
}

__global__ void zero_kernel() {
    const int idx = blockIdx.x * 256 + threadIdx.x;  // < SZH
    g_h0[idx] = 0.f; g_h1[idx] = 0.f; g_c0[idx] = 0.f; g_c1[idx] = 0.f;
}

// ---------------- fused warp-specialized cell kernel ----------------
// 384 threads: warps 0..7 = GEMM, warps 8..11 = SpMM gather.
// Slots in smem (2048 floats each): 0=Ah_A, 1=h_A, [2=Ah_B, 3=h_B layer1].
// comb = [slots] @ Wcat; h-slots (1,3) are computed WHILE gather warps fill
// Ah-slots (0,2); a block-wide barrier separates the halves. W is read
// straight from global (L1-resident: 8 warps sweep the same rows together).
template<int LAYER>
__global__ void __launch_bounds__(384) cell_kernel(int pi, int t)
{
    constexpr int NSRC = (LAYER == 0) ? 1 : 2;
    __shared__ float buf[8192];   // src slots; overlaid by comb [32x256] at the end

    const int po = pi ^ 1;
    const float* __restrict__ hA   = (LAYER == 0) ? (g_h0 + pi*SZH) : (g_h0 + po*SZH);
    const float* __restrict__ hB   = g_h1 + pi*SZH;
    float*       __restrict__ hout = (LAYER == 0) ? (g_h0 + po*SZH) : (g_h1 + po*SZH);
    float*       __restrict__ cst  = (LAYER == 0) ? g_c0 : g_c1;
    const float* __restrict__ WCAT = (LAYER == 0) ? g_W0 : g_W1;
    const float* __restrict__ btot = (LAYER == 0) ? g_b0 : g_b1;

    const int tid  = threadIdx.x;
    const int lane = tid & 31, warp = tid >> 5;
    const int r0   = blockIdx.x * 32;

    // stage h slots (all threads)
    for (int i = tid; i < 2048; i += 384) {
        buf[2048 + i] = hA[r0*64 + i];
        if (NSRC == 2) buf[6144 + i] = hB[r0*64 + i];
    }
    __syncthreads();                                   // #1

    if (warp >= 8) {
        // ---------------- gather warps: SpMM into Ah slots ----------------
        const int gw = warp - 8;                        // 0..3
        for (int rr = gw; rr < 32; rr += 4) {
            const int r = r0 + rr;
            const int cn = g_cnt[r];
            const int*   cp = g_cols + r*MAXNZ;
            const float* vp = g_vals + r*MAXNZ;
            float a00 = 0.f, a01 = 0.f, a10 = 0.f, a11 = 0.f;
            int k = 0;
            #pragma unroll 1
            for (; k + 8 <= cn; k += 8) {
                int   cc[8]; float vv[8];
                #pragma unroll
                for (int u = 0; u < 8; u++) { cc[u] = cp[k+u]; vv[u] = vp[k+u]; }
                #pragma unroll
                for (int u = 0; u < 8; u++) {
                    const float* hr = hA + cc[u]*64;
                    a00 += vv[u]*hr[lane];
                    a01 += vv[u]*hr[lane+32];
                    if (NSRC == 2) {
                        const float* hs = hB + cc[u]*64;
                        a10 += vv[u]*hs[lane];
                        a11 += vv[u]*hs[lane+32];
                    }
                }
            }
            for (; k < cn; k++) {
                const int c = cp[k]; const float v = vp[k];
                a00 += v*hA[c*64+lane]; a01 += v*hA[c*64+lane+32];
                if (NSRC == 2) { a10 += v*hB[c*64+lane]; a11 += v*hB[c*64+lane+32]; }
            }
            buf[rr*64 + lane] = a00; buf[rr*64 + lane + 32] = a01;
            if (NSRC == 2) {
                buf[4096 + rr*64 + lane] = a10; buf[4096 + rr*64 + lane + 32] = a11;
            }
        }
        __syncthreads();                               // #2 (Ah published)
        __syncthreads();                               // #3 (GEMM reads done)
        __syncthreads();                               // #4 (comb published)
    } else {
        // ---------------- GEMM warps: comb = src @ Wcat ----------------
        const int rb  = tid >> 5;                      // 0..7 -> rows rb*4..+3
        const int cb  = tid & 31;
        const int ca  = cb * 4;                        // cols [ca, ca+4)
        const int cbx = 128 + cb * 4;                  // cols [cbx, cbx+4)
        float acc[4][8];
        {
            const float4 b0 = *(const float4*)(btot + ca);
            const float4 b1 = *(const float4*)(btot + cbx);
            #pragma unroll
            for (int rr = 0; rr < 4; rr++) {
                acc[rr][0]=b0.x; acc[rr][1]=b0.y; acc[rr][2]=b0.z; acc[rr][3]=b0.w;
                acc[rr][4]=b1.x; acc[rr][5]=b1.y; acc[rr][6]=b1.z; acc[rr][7]=b1.w;
            }
        }

        auto gemm_slot = [&](int slot) {
            const float* __restrict__ srcp = buf + slot * 2048;
            const float* __restrict__ Wp   = WCAT + slot * 16384;  // 64 K-rows
            #pragma unroll 2
            for (int k0 = 0; k0 < 64; k0 += 4) {
                float4 av[4];
                #pragma unroll
                for (int rr = 0; rr < 4; rr++)
                    av[rr] = *(const float4*)(srcp + (rb*4+rr)*64 + k0);
                #pragma unroll
                for (int kk = 0; kk < 4; kk++) {
                    const float4 w0 = __ldg((const float4*)(Wp + (k0+kk)*256 + ca));
                    const float4 w1 = __ldg((const float4*)(Wp + (k0+kk)*256 + cbx));
                    #pragma unroll
                    for (int rr = 0; rr < 4; rr++) {
                        const float a = (kk==0)?av[rr].x:(kk==1)?av[rr].y
                                       :(kk==2)?av[rr].z:av[rr].w;
                        acc[rr][0] += a*w0.x; acc[rr][1] += a*w0.y;
                        acc[rr][2] += a*w0.z; acc[rr][3] += a*w0.w;
                        acc[rr][4] += a*w1.x; acc[rr][5] += a*w1.y;
                        acc[rr][6] += a*w1.z; acc[rr][7] += a*w1.w;
                    }
                }
            }
        };

        // h-half (independent of gather), overlapped with SpMM
        gemm_slot(1);
        if (NSRC == 2) gemm_slot(3);
        __syncthreads();                               // #2 (wait for Ah)
        gemm_slot(0);
        if (NSRC == 2) gemm_slot(2);

        if (LAYER == 0) {   // rank-2 x terms: (A x_t)@gcWi0 + x_t@liWi0
            float4 wxa[4], wxb[4];
            #pragma unroll
            for (int j = 0; j < 4; j++) {
                wxa[j] = *(const float4*)(g_WX + j*256 + ca);
                wxb[j] = *(const float4*)(g_WX + j*256 + cbx);
            }
            #pragma unroll
            for (int rr = 0; rr < 4; rr++) {
                const int r = r0 + rb*4 + rr;
                const float s0 = g_AX  [r*96 + 2*t];
                const float s1 = g_AX  [r*96 + 2*t + 1];
                const float s2 = g_Xall[r*96 + 2*t];
                const float s3 = g_Xall[r*96 + 2*t + 1];
                acc[rr][0] += s0*wxa[0].x + s1*wxa[1].x + s2*wxa[2].x + s3*wxa[3].x;
                acc[rr][1] += s0*wxa[0].y + s1*wxa[1].y + s2*wxa[2].y + s3*wxa[3].y;
                acc[rr][2] += s0*wxa[0].z + s1*wxa[1].z + s2*wxa[2].z + s3*wxa[3].z;
                acc[rr][3] += s0*wxa[0].w + s1*wxa[1].w + s2*wxa[2].w + s3*wxa[3].w;
                acc[rr][4] += s0*wxb[0].x + s1*wxb[1].x + s2*wxb[2].x + s3*wxb[3].x;
                acc[rr][5] += s0*wxb[0].y + s1*wxb[1].y + s2*wxb[2].y + s3*wxb[3].y;
                acc[rr][6] += s0*wxb[0].z + s1*wxb[1].z + s2*wxb[2].z + s3*wxb[3].z;
                acc[rr][7] += s0*wxb[0].w + s1*wxb[1].w + s2*wxb[2].w + s3*wxb[3].w;
            }
        }

        __syncthreads();                               // #3 (all src reads done)
        #pragma unroll
        for (int rr = 0; rr < 4; rr++) {
            *(float4*)(buf + (rb*4+rr)*256 + ca)  =
                make_float4(acc[rr][0], acc[rr][1], acc[rr][2], acc[rr][3]);
            *(float4*)(buf + (rb*4+rr)*256 + cbx) =
                make_float4(acc[rr][4], acc[rr][5], acc[rr][6], acc[rr][7]);
        }
        __syncthreads();                               // #4 (comb published)
    }

    // ---- gates (all 384 threads) ----
    for (int i = tid; i < 2048; i += 384) {
        const int n = i >> 6, hc = i & 63;
        const float ig = buf[n*256 + hc];
        const float fg = buf[n*256 + 64  + hc];
        const float og = buf[n*256 + 128 + hc];
        const float gg = buf[n*256 + 192 + hc];
        const int g = (r0 + n)*64 + hc;
        const float cold = cst[g];
        const float cnew = sigf(fg)*cold + sigf(ig)*tanhf(gg);
        cst[g]  = cnew;
        hout[g] = sigf(og)*tanhf(cnew);
    }
}

// out[n,p] = h1_final[n,:] @ outW + outb
__global__ void outproj_kernel(const float* __restrict__ outW,
                               const float* __restrict__ outb,
                               float* __restrict__ out) {
    const int idx = blockIdx.x*blockDim.x + threadIdx.x;
    if (idx >= NN*12) return;
    const int n = idx / 12, p = idx - n*12;
    const float* h = g_h1 + n*64;    // final ping index 0 after t=47
    float s = outb[p];
    #pragma unroll
    for (int k = 0; k < 64; k++) s += h[k] * outW[k*12 + p];
    out[idx] = s;
}

// ---------------- launch ----------------
extern "C" void kernel_launch(void* const* d_in, const int* in_sizes, int n_in,
                              void* d_out, int out_size) {
    (void)in_sizes; (void)n_in; (void)out_size;
    const float* x     = (const float*)d_in[0];
    const float* adj   = (const float*)d_in[1];
    const float* gcWi0 = (const float*)d_in[2];
    const float* gcbi0 = (const float*)d_in[3];
    const float* gcWh0 = (const float*)d_in[4];
    const float* gcbh0 = (const float*)d_in[5];
    const float* liWi0 = (const float*)d_in[6];
    const float* libi0 = (const float*)d_in[7];
    const float* liWh0 = (const float*)d_in[8];
    const float* libh0 = (const float*)d_in[9];
    const float* gcWi1 = (const float*)d_in[10];
    const float* gcbi1 = (const float*)d_in[11];
    const float* gcWh1 = (const float*)d_in[12];
    const float* gcbh1 = (const float*)d_in[13];
    const float* liWi1 = (const float*)d_in[14];
    const float* libi1 = (const float*)d_in[15];
    const float* liWh1 = (const float*)d_in[16];
    const float* libh1 = (const float*)d_in[17];
    const float* outW  = (const float*)d_in[18];
    const float* outb  = (const float*)d_in[19];
    float* out = (float*)d_out;

    deg_kernel <<<NN, 256>>>(adj);
    ell_kernel <<<NN/8, 256>>>(adj);
    xall_kernel<<<(NN*96)/256, 256>>>(x);
    spmm96_kernel<<<NN/8, 256>>>();
    setup_kernel<<<64, 256>>>(gcWi0, liWi0, gcWh0, liWh0,
                              gcWi1, liWi1, gcWh1, liWh1,
                              gcbi0, gcbh0, libi0, libh0,
                              gcbi1, gcbh1, libi1, libh1);
    zero_kernel<<<SZH/256, 256>>>();

    for (int t = 0; t < TT; t++) {
        const int pi = t & 1;
        cell_kernel<0><<<NN/32, 384>>>(pi, t);
        cell_kernel<1><<<NN/32, 384>>>(pi, t);
    }
    outproj_kernel<<<(NN*12 + 255)/256, 256>>>(outW, outb, out);
}

// round 4
// speedup vs baseline: 1.3710x; 1.3710x over previous
#include <cuda_runtime.h>
#include <cuda_bf16.h>
#include <math.h>

#define NN 4096
#define TT 48
#define MAXNZ 128
#define SZH (NN*64)

// ---------------- device scratch (static, no allocation) ----------------
__device__ float g_dinv[NN];
__device__ int   g_cnt[NN];
__device__ int   g_cols[NN*MAXNZ];
__device__ float g_vals[NN*MAXNZ];
__device__ float g_Xall[NN*96];
__device__ float g_AX[NN*96];
__device__ float g_h0[2*SZH];
__device__ float g_h1[2*SZH];
__device__ float g_c0[SZH];
__device__ float g_c1[SZH];
__device__ float g_b0[256];
__device__ float g_b1[256];
__device__ float g_WX[4*256];                 // [gcWi0 rows 0,1 ; liWi0 rows 0,1]
__device__ __align__(16) unsigned g_Wf0[32768];  // layer0 W frags (K=128)
__device__ __align__(16) unsigned g_Wf1[65536];  // layer1 W frags (K=256)

__device__ __forceinline__ float sigf(float x) { return 1.0f / (1.0f + expf(-x)); }

// bf16 mma: D += A(16x16) * B(16x8), fp32 accum
#define MMA_BF16(C, A, b0, b1) \
    asm volatile("mma.sync.aligned.m16n8k16.row.col.f32.bf16.bf16.f32 " \
        "{%0,%1,%2,%3}, {%4,%5,%6,%7}, {%8,%9}, {%0,%1,%2,%3};" \
        : "+f"(C[0]), "+f"(C[1]), "+f"(C[2]), "+f"(C[3]) \
        : "r"(A[0]), "r"(A[1]), "r"(A[2]), "r"(A[3]), "r"(b0), "r"(b1))

// ---------------- setup kernels ----------------

__global__ void deg_kernel(const float* __restrict__ adj) {
    __shared__ float red[256];
    const int r = blockIdx.x;
    float s = 0.0f;
    for (int c = threadIdx.x; c < NN; c += 256) s += adj[(long)r*NN + c];
    red[threadIdx.x] = s;
    __syncthreads();
    for (int o = 128; o > 0; o >>= 1) {
        if (threadIdx.x < o) red[threadIdx.x] += red[threadIdx.x + o];
        __syncthreads();
    }
    if (threadIdx.x == 0) g_dinv[r] = 1.0f / sqrtf(red[0] + 1.0f);
}

__global__ void ell_kernel(const float* __restrict__ adj) {
    const int lane = threadIdx.x & 31;
    const int r = blockIdx.x * 8 + (threadIdx.x >> 5);
    const float dr = g_dinv[r];
    int base = 0;
    for (int c0 = 0; c0 < NN; c0 += 32) {
        const int c = c0 + lane;
        float a = adj[(long)r*NN + c];
        if (c == r) a += 1.0f;
        const unsigned m = __ballot_sync(0xffffffffu, a != 0.0f);
        if (a != 0.0f) {
            const int pos = base + __popc(m & ((1u << lane) - 1u));
            if (pos < MAXNZ) {
                g_cols[r*MAXNZ + pos] = c;
                g_vals[r*MAXNZ + pos] = a * dr * g_dinv[c];
            }
        }
        base += __popc(m);
    }
    if (lane == 0) g_cnt[r] = (base < MAXNZ) ? base : MAXNZ;
}

__global__ void xall_kernel(const float* __restrict__ x) {
    const int idx = blockIdx.x * 256 + threadIdx.x;   // < NN*96
    const int n = idx / 96;
    const int q = idx - n * 96;
    const int t = q >> 1, i = q & 1;
    g_Xall[idx] = x[t * (NN*2) + n*2 + i];
}

__global__ void spmm96_kernel() {
    const int lane = threadIdx.x & 31;
    const int r = blockIdx.x * 8 + (threadIdx.x >> 5);
    const int cn = g_cnt[r];
    const int*   cp = g_cols + r*MAXNZ;
    const float* vp = g_vals + r*MAXNZ;
    float a0 = 0.f, a1 = 0.f, a2 = 0.f;
    for (int k = 0; k < cn; k++) {
        const int c = cp[k]; const float v = vp[k];
        a0 += v * g_Xall[c*96 + lane];
        a1 += v * g_Xall[c*96 + lane + 32];
        a2 += v * g_Xall[c*96 + lane + 64];
    }
    g_AX[r*96 + lane]      = a0;
    g_AX[r*96 + lane + 32] = a1;
    g_AX[r*96 + lane + 64] = a2;
}

// Build W in bf16x2 hi/lo fragment-linear layout.
// idx layout within layer: (((ks*32 + nt)*2 + b)*2 + hl)*32 + lane
// element pair: k = ks*16 + b*8 + 2*tig (+1), n = nt*8 + g  (lane = g*4 + tig)
__global__ void wfrag_kernel(
    const float* __restrict__ gcWh0, const float* __restrict__ liWh0,
    const float* __restrict__ gcWi1, const float* __restrict__ liWi1,
    const float* __restrict__ gcWh1, const float* __restrict__ liWh1)
{
    const int idx = blockIdx.x * 256 + threadIdx.x;    // < 98304
    if (idx >= 98304) return;
    const int L = (idx >= 32768);
    const int j = L ? idx - 32768 : idx;
    const int lane = j & 31, hl = (j >> 5) & 1, b = (j >> 6) & 1;
    const int nt = (j >> 7) & 31, ks = j >> 12;
    const int g = lane >> 2, tig = lane & 3;
    const int k0 = ks*16 + b*8 + 2*tig;
    const int n  = nt*8 + g;
    unsigned short h2[2];
    #pragma unroll
    for (int e = 0; e < 2; e++) {
        const int k = k0 + e;
        const float* src;
        if (!L) src = (k < 64) ? (gcWh0 + k*256) : (liWh0 + (k-64)*256);
        else {
            const int q = k >> 6;
            src = (q == 0) ? (gcWi1 + k*256)
                : (q == 1) ? (liWi1 + (k-64)*256)
                : (q == 2) ? (gcWh1 + (k-128)*256)
                           : (liWh1 + (k-192)*256);
        }
        const float w = src[n];
        __nv_bfloat16 bh = __float2bfloat16(w);
        if (hl) bh = __float2bfloat16(w - __bfloat162float(bh));
        h2[e] = __bfloat16_as_ushort(bh);
    }
    const unsigned val = (unsigned)h2[0] | ((unsigned)h2[1] << 16);
    if (L) g_Wf1[j] = val; else g_Wf0[j] = val;
}

__global__ void bias_kernel(
    const float* __restrict__ gcWi0, const float* __restrict__ liWi0,
    const float* __restrict__ gcbi0, const float* __restrict__ gcbh0,
    const float* __restrict__ libi0, const float* __restrict__ libh0,
    const float* __restrict__ gcbi1, const float* __restrict__ gcbh1,
    const float* __restrict__ libi1, const float* __restrict__ libh1)
{
    const int c = threadIdx.x;   // 256
    g_b0[c] = gcbi0[c] + gcbh0[c] + libi0[c] + libh0[c];
    g_b1[c] = gcbi1[c] + gcbh1[c] + libi1[c] + libh1[c];
    g_WX[c]       = gcWi0[c];
    g_WX[256 + c] = gcWi0[256 + c];
    g_WX[512 + c] = liWi0[c];
    g_WX[768 + c] = liWi0[256 + c];
}

__global__ void zero_kernel() {
    const int idx = blockIdx.x * 256 + threadIdx.x;  // < SZH
    g_h0[idx] = 0.f; g_h1[idx] = 0.f; g_c0[idx] = 0.f; g_c1[idx] = 0.f;
}

// ---------------- fused cell kernel (tensor-core GEMM) ----------------
// 256 threads. Phase 1: stage h (bf16 hi/lo) + SpMM gather Ah (fp32 accum ->
// bf16 hi/lo) into padded smem slots. Phase 2: comb = src @ Wcat with
// mma.sync.m16n8k16.bf16 (x3 split: hh + h*lo + lo*h). W fragments staged
// per-64-K-rows chunk from pre-swizzled gmem. Phase 3: gates.
template<int LAYER>
__global__ void __launch_bounds__(256) cell_kernel(int pi, int t)
{
    constexpr int NSRC  = (LAYER == 0) ? 1 : 2;
    constexpr int SLOTS = 2*NSRC;
    constexpr int HALF  = 32*72;                 // bf16 elems per slot-half
    constexpr int SRC_BYTES = SLOTS*2*HALF*2;
    extern __shared__ char smem[];
    __nv_bfloat16* s_src = (__nv_bfloat16*)smem;              // [slot*2+hl][32*72]
    unsigned*      s_w   = (unsigned*)(smem + SRC_BYTES);     // 16384 u32
    float*         s_comb= (float*)(smem + SRC_BYTES + 65536);// 32*256 f32

    const int po = pi ^ 1;
    const float* __restrict__ hA   = (LAYER == 0) ? (g_h0 + pi*SZH) : (g_h0 + po*SZH);
    const float* __restrict__ hB   = g_h1 + pi*SZH;
    float*       __restrict__ hout = (LAYER == 0) ? (g_h0 + po*SZH) : (g_h1 + po*SZH);
    float*       __restrict__ cst  = (LAYER == 0) ? g_c0 : g_c1;
    const float* __restrict__ btot = (LAYER == 0) ? g_b0 : g_b1;
    const unsigned* __restrict__ WF = (LAYER == 0) ? g_Wf0 : g_Wf1;

    const int tid = threadIdx.x, lane = tid & 31, warp = tid >> 5;
    const int r0 = blockIdx.x * 32;

    // ---- stage h slots (slot 1 = hA; slot 3 = hB) as bf16 hi/lo ----
    for (int i = tid; i < 2048; i += 256) {
        const int n = i >> 6, c = i & 63;
        float v = hA[(r0 + n)*64 + c];
        __nv_bfloat16 hi = __float2bfloat16(v);
        __nv_bfloat16 lo = __float2bfloat16(v - __bfloat162float(hi));
        s_src[(1*2+0)*HALF + n*72 + c] = hi;
        s_src[(1*2+1)*HALF + n*72 + c] = lo;
        if (NSRC == 2) {
            v = hB[(r0 + n)*64 + c];
            hi = __float2bfloat16(v);
            lo = __float2bfloat16(v - __bfloat162float(hi));
            s_src[(3*2+0)*HALF + n*72 + c] = hi;
            s_src[(3*2+1)*HALF + n*72 + c] = lo;
        }
    }

    // ---- SpMM gather: Ah -> slot 0 (and slot 2) ----
    for (int rr = warp; rr < 32; rr += 8) {
        const int r = r0 + rr;
        const int cn = g_cnt[r];
        const int*   cp = g_cols + r*MAXNZ;
        const float* vp = g_vals + r*MAXNZ;
        float a00 = 0.f, a01 = 0.f, a10 = 0.f, a11 = 0.f;
        int k = 0;
        #pragma unroll 1
        for (; k + 4 <= cn; k += 4) {
            const int   c0 = cp[k],   c1 = cp[k+1], c2 = cp[k+2], c3 = cp[k+3];
            const float v0 = vp[k],   v1 = vp[k+1], v2 = vp[k+2], v3 = vp[k+3];
            a00 += v0*hA[c0*64+lane]    + v1*hA[c1*64+lane]
                 + v2*hA[c2*64+lane]    + v3*hA[c3*64+lane];
            a01 += v0*hA[c0*64+lane+32] + v1*hA[c1*64+lane+32]
                 + v2*hA[c2*64+lane+32] + v3*hA[c3*64+lane+32];
            if (NSRC == 2) {
                a10 += v0*hB[c0*64+lane]    + v1*hB[c1*64+lane]
                     + v2*hB[c2*64+lane]    + v3*hB[c3*64+lane];
                a11 += v0*hB[c0*64+lane+32] + v1*hB[c1*64+lane+32]
                     + v2*hB[c2*64+lane+32] + v3*hB[c3*64+lane+32];
            }
        }
        for (; k < cn; k++) {
            const int c = cp[k]; const float v = vp[k];
            a00 += v*hA[c*64+lane]; a01 += v*hA[c*64+lane+32];
            if (NSRC == 2) { a10 += v*hB[c*64+lane]; a11 += v*hB[c*64+lane+32]; }
        }
        {
            __nv_bfloat16 h0 = __float2bfloat16(a00);
            __nv_bfloat16 l0 = __float2bfloat16(a00 - __bfloat162float(h0));
            __nv_bfloat16 h1 = __float2bfloat16(a01);
            __nv_bfloat16 l1 = __float2bfloat16(a01 - __bfloat162float(h1));
            s_src[0*HALF + rr*72 + lane]      = h0;
            s_src[1*HALF + rr*72 + lane]      = l0;
            s_src[0*HALF + rr*72 + lane + 32] = h1;
            s_src[1*HALF + rr*72 + lane + 32] = l1;
            if (NSRC == 2) {
                h0 = __float2bfloat16(a10);
                l0 = __float2bfloat16(a10 - __bfloat162float(h0));
                h1 = __float2bfloat16(a11);
                l1 = __float2bfloat16(a11 - __bfloat162float(h1));
                s_src[(2*2+0)*HALF + rr*72 + lane]      = h0;
                s_src[(2*2+1)*HALF + rr*72 + lane]      = l0;
                s_src[(2*2+0)*HALF + rr*72 + lane + 32] = h1;
                s_src[(2*2+1)*HALF + rr*72 + lane + 32] = l1;
            }
        }
    }

    // ---- tensor-core GEMM ----
    const int g = lane >> 2, tig = lane & 3;
    const int m0  = (warp & 1) * 16;     // 16-row tile
    const int ng0 = (warp >> 1) * 8;     // 8 n-tiles (64 cols)
    float acc[8][4];
    #pragma unroll
    for (int nt = 0; nt < 8; nt++) {
        const int col = (ng0 + nt)*8 + 2*tig;
        const float b0v = btot[col], b1v = btot[col+1];
        acc[nt][0] = b0v; acc[nt][1] = b1v; acc[nt][2] = b0v; acc[nt][3] = b1v;
    }

    #pragma unroll
    for (int slot = 0; slot < SLOTS; slot++) {
        __syncthreads();                            // gather done / W buf free
        {   // stage this slot's W frag chunk (64 K-rows = 16384 u32)
            const float4* gw = (const float4*)(WF + slot*16384);
            float4* sw = (float4*)s_w;
            #pragma unroll
            for (int i = 0; i < 16; i++) sw[tid + i*256] = gw[tid + i*256];
        }
        __syncthreads();
        const __nv_bfloat16* ah = s_src + (slot*2+0)*HALF;
        const __nv_bfloat16* al = s_src + (slot*2+1)*HALF;
        #pragma unroll
        for (int ks = 0; ks < 4; ks++) {
            unsigned Ah[4], Al[4];
            const int ab = (m0 + g)*72 + ks*16 + 2*tig;
            Ah[0] = *(const unsigned*)(ah + ab);
            Ah[1] = *(const unsigned*)(ah + ab + 8*72);
            Ah[2] = *(const unsigned*)(ah + ab + 8);
            Ah[3] = *(const unsigned*)(ah + ab + 8*72 + 8);
            Al[0] = *(const unsigned*)(al + ab);
            Al[1] = *(const unsigned*)(al + ab + 8*72);
            Al[2] = *(const unsigned*)(al + ab + 8);
            Al[3] = *(const unsigned*)(al + ab + 8*72 + 8);
            const unsigned* wp = s_w + ks*4096 + ng0*128 + lane;
            #pragma unroll
            for (int nt = 0; nt < 8; nt++) {
                const unsigned b0h = wp[nt*128];
                const unsigned b1h = wp[nt*128 + 64];
                const unsigned b0l = wp[nt*128 + 32];
                const unsigned b1l = wp[nt*128 + 96];
                MMA_BF16(acc[nt], Ah, b0h, b1h);
                MMA_BF16(acc[nt], Ah, b0l, b1l);
                MMA_BF16(acc[nt], Al, b0h, b1h);
            }
        }
    }

    if (LAYER == 0) {   // rank-2 x terms in fp32: (A x_t)@gcWi0 + x_t@liWi0
        const int rA = r0 + m0 + g, rB = rA + 8;
        float sA[4], sB[4];
        sA[0] = g_AX  [rA*96 + 2*t]; sA[1] = g_AX  [rA*96 + 2*t + 1];
        sA[2] = g_Xall[rA*96 + 2*t]; sA[3] = g_Xall[rA*96 + 2*t + 1];
        sB[0] = g_AX  [rB*96 + 2*t]; sB[1] = g_AX  [rB*96 + 2*t + 1];
        sB[2] = g_Xall[rB*96 + 2*t]; sB[3] = g_Xall[rB*96 + 2*t + 1];
        #pragma unroll
        for (int nt = 0; nt < 8; nt++) {
            const int col = (ng0 + nt)*8 + 2*tig;
            #pragma unroll
            for (int jx = 0; jx < 4; jx++) {
                const float w0 = g_WX[jx*256 + col], w1 = g_WX[jx*256 + col + 1];
                acc[nt][0] += sA[jx]*w0; acc[nt][1] += sA[jx]*w1;
                acc[nt][2] += sB[jx]*w0; acc[nt][3] += sB[jx]*w1;
            }
        }
    }

    // ---- write comb to smem, then gates ----
    #pragma unroll
    for (int nt = 0; nt < 8; nt++) {
        const int col = (ng0 + nt)*8 + 2*tig;
        *(float2*)(s_comb + (m0 + g)*256 + col)     = make_float2(acc[nt][0], acc[nt][1]);
        *(float2*)(s_comb + (m0 + g + 8)*256 + col) = make_float2(acc[nt][2], acc[nt][3]);
    }
    __syncthreads();
    for (int i = tid; i < 2048; i += 256) {
        const int n = i >> 6, hc = i & 63;
        const float ig = s_comb[n*256 + hc];
        const float fg = s_comb[n*256 + 64  + hc];
        const float og = s_comb[n*256 + 128 + hc];
        const float gg = s_comb[n*256 + 192 + hc];
        const int gi = (r0 + n)*64 + hc;
        const float cold = cst[gi];
        const float cnew = sigf(fg)*cold + sigf(ig)*tanhf(gg);
        cst[gi]  = cnew;
        hout[gi] = sigf(og)*tanhf(cnew);
    }
}

// out[n,p] = h1_final[n,:] @ outW + outb
__global__ void outproj_kernel(const float* __restrict__ outW,
                               const float* __restrict__ outb,
                               float* __restrict__ out) {
    const int idx = blockIdx.x*blockDim.x + threadIdx.x;
    if (idx >= NN*12) return;
    const int n = idx / 12, p = idx - n*12;
    const float* h = g_h1 + n*64;    // final ping index 0 after t=47
    float s = outb[p];
    #pragma unroll
    for (int k = 0; k < 64; k++) s += h[k] * outW[k*12 + p];
    out[idx] = s;
}

// ---------------- launch ----------------
extern "C" void kernel_launch(void* const* d_in, const int* in_sizes, int n_in,
                              void* d_out, int out_size) {
    (void)in_sizes; (void)n_in; (void)out_size;
    const float* x     = (const float*)d_in[0];
    const float* adj   = (const float*)d_in[1];
    const float* gcWi0 = (const float*)d_in[2];
    const float* gcbi0 = (const float*)d_in[3];
    const float* gcWh0 = (const float*)d_in[4];
    const float* gcbh0 = (const float*)d_in[5];
    const float* liWi0 = (const float*)d_in[6];
    const float* libi0 = (const float*)d_in[7];
    const float* liWh0 = (const float*)d_in[8];
    const float* libh0 = (const float*)d_in[9];
    const float* gcWi1 = (const float*)d_in[10];
    const float* gcbi1 = (const float*)d_in[11];
    const float* gcWh1 = (const float*)d_in[12];
    const float* gcbh1 = (const float*)d_in[13];
    const float* liWi1 = (const float*)d_in[14];
    const float* libi1 = (const float*)d_in[15];
    const float* liWh1 = (const float*)d_in[16];
    const float* libh1 = (const float*)d_in[17];
    const float* outW  = (const float*)d_in[18];
    const float* outb  = (const float*)d_in[19];
    float* out = (float*)d_out;

    const int SMEM0 = 4*32*72*2 + 65536 + 32768;   // 116736
    const int SMEM1 = 8*32*72*2 + 65536 + 32768;   // 135168
    cudaFuncSetAttribute(cell_kernel<0>, cudaFuncAttributeMaxDynamicSharedMemorySize, SMEM0);
    cudaFuncSetAttribute(cell_kernel<1>, cudaFuncAttributeMaxDynamicSharedMemorySize, SMEM1);

    deg_kernel <<<NN, 256>>>(adj);
    ell_kernel <<<NN/8, 256>>>(adj);
    xall_kernel<<<(NN*96)/256, 256>>>(x);
    spmm96_kernel<<<NN/8, 256>>>();
    wfrag_kernel<<<384, 256>>>(gcWh0, liWh0, gcWi1, liWi1, gcWh1, liWh1);
    bias_kernel<<<1, 256>>>(gcWi0, liWi0, gcbi0, gcbh0, libi0, libh0,
                            gcbi1, gcbh1, libi1, libh1);
    zero_kernel<<<SZH/256, 256>>>();

    for (int t = 0; t < TT; t++) {
        const int pi = t & 1;
        cell_kernel<0><<<NN/32, 256, SMEM0>>>(pi, t);
        cell_kernel<1><<<NN/32, 256, SMEM1>>>(pi, t);
    }
    outproj_kernel<<<(NN*12 + 255)/256, 256>>>(outW, outb, out);
}

// round 7
// speedup vs baseline: 2.0637x; 1.5052x over previous
#include <cuda_runtime.h>
#include <cuda_bf16.h>
#include <math.h>

#define NN 4096
#define TT 48
#define MAXNZ 128
#define SZH (NN*64)

// ---------------- device scratch (static, no allocation) ----------------
__device__ float g_dinv[NN];
__device__ int   g_cnt[NN];
__device__ int   g_cols[NN*MAXNZ];
__device__ float g_vals[NN*MAXNZ];
__device__ float g_Xall[NN*96];
__device__ float g_AX[NN*96];
__device__ float g_h0[2*SZH];
__device__ float g_h1[2*SZH];
__device__ float g_c0[SZH];
__device__ float g_c1[SZH];
__device__ float g_b0[256];
__device__ float g_b1[256];
__device__ float g_WX[4*256];                    // [gcWi0 rows 0,1 ; liWi0 rows 0,1]
__device__ __align__(16) unsigned g_Wf0[32768];  // layer0 W frags (K=128)
__device__ __align__(16) unsigned g_Wf1[65536];  // layer1 W frags (K=256)

__device__ __forceinline__ float sigf(float x) { return 1.0f / (1.0f + expf(-x)); }

// bf16 mma: D += A(16x16) * B(16x8), fp32 accum
#define MMA_BF16(C, A, b0, b1) \
    asm volatile("mma.sync.aligned.m16n8k16.row.col.f32.bf16.bf16.f32 " \
        "{%0,%1,%2,%3}, {%4,%5,%6,%7}, {%8,%9}, {%0,%1,%2,%3};" \
        : "+f"(C[0]), "+f"(C[1]), "+f"(C[2]), "+f"(C[3]) \
        : "r"(A[0]), "r"(A[1]), "r"(A[2]), "r"(A[3]), "r"(b0), "r"(b1))

__device__ __forceinline__ void cp_async16(void* s, const void* g) {
    unsigned sa = (unsigned)__cvta_generic_to_shared(s);
    asm volatile("cp.async.ca.shared.global [%0], [%1], 16;" :: "r"(sa), "l"(g));
}
__device__ __forceinline__ void cp_commit() {
    asm volatile("cp.async.commit_group;");
}
template<int Nq> __device__ __forceinline__ void cp_wait() {
    asm volatile("cp.async.wait_group %0;" :: "n"(Nq));
}

// pack float2 -> bf16 hi-pair + lo-pair (residual), store as u32 each
__device__ __forceinline__ void store_hilo(__nv_bfloat16* bhi, __nv_bfloat16* blo,
                                           int off, float2 v) {
    const __nv_bfloat16 hx = __float2bfloat16(v.x), hy = __float2bfloat16(v.y);
    const float rx = v.x - __bfloat162float(hx);
    const float ry = v.y - __bfloat162float(hy);
    const unsigned uh = (unsigned)__bfloat16_as_ushort(hx)
                      | ((unsigned)__bfloat16_as_ushort(hy) << 16);
    const unsigned ul = (unsigned)__bfloat16_as_ushort(__float2bfloat16(rx))
                      | ((unsigned)__bfloat16_as_ushort(__float2bfloat16(ry)) << 16);
    *(unsigned*)(bhi + off) = uh;
    *(unsigned*)(blo + off) = ul;
}

// ---------------- setup kernels ----------------

__global__ void deg_kernel(const float* __restrict__ adj) {
    __shared__ float red[256];
    const int r = blockIdx.x;
    float s = 0.0f;
    for (int c = threadIdx.x; c < NN; c += 256) s += adj[(long)r*NN + c];
    red[threadIdx.x] = s;
    __syncthreads();
    for (int o = 128; o > 0; o >>= 1) {
        if (threadIdx.x < o) red[threadIdx.x] += red[threadIdx.x + o];
        __syncthreads();
    }
    if (threadIdx.x == 0) g_dinv[r] = 1.0f / sqrtf(red[0] + 1.0f);
}

__global__ void ell_kernel(const float* __restrict__ adj) {
    const int lane = threadIdx.x & 31;
    const int r = blockIdx.x * 8 + (threadIdx.x >> 5);
    const float dr = g_dinv[r];
    int base = 0;
    for (int c0 = 0; c0 < NN; c0 += 32) {
        const int c = c0 + lane;
        float a = adj[(long)r*NN + c];
        if (c == r) a += 1.0f;
        const unsigned m = __ballot_sync(0xffffffffu, a != 0.0f);
        if (a != 0.0f) {
            const int pos = base + __popc(m & ((1u << lane) - 1u));
            if (pos < MAXNZ) {
                g_cols[r*MAXNZ + pos] = c;
                g_vals[r*MAXNZ + pos] = a * dr * g_dinv[c];
            }
        }
        base += __popc(m);
    }
    if (lane == 0) g_cnt[r] = (base < MAXNZ) ? base : MAXNZ;
}

// merged: Xall transpose + state zeroing
__global__ void xallzero_kernel(const float* __restrict__ x) {
    const int idx = blockIdx.x * 256 + threadIdx.x;   // < NN*96
    const int n = idx / 96;
    const int q = idx - n * 96;
    const int t = q >> 1, i = q & 1;
    g_Xall[idx] = x[t * (NN*2) + n*2 + i];
    if (idx < SZH) {
        g_h0[idx] = 0.f; g_h0[SZH + idx] = 0.f;
        g_h1[idx] = 0.f; g_h1[SZH + idx] = 0.f;
        g_c0[idx] = 0.f; g_c1[idx] = 0.f;
    }
}

__global__ void spmm96_kernel() {
    const int lane = threadIdx.x & 31;
    const int r = blockIdx.x * 8 + (threadIdx.x >> 5);
    const int cn = g_cnt[r];
    const int*   cp = g_cols + r*MAXNZ;
    const float* vp = g_vals + r*MAXNZ;
    float a0 = 0.f, a1 = 0.f, a2 = 0.f;
    for (int k = 0; k < cn; k++) {
        const int c = cp[k]; const float v = vp[k];
        a0 += v * g_Xall[c*96 + lane];
        a1 += v * g_Xall[c*96 + lane + 32];
        a2 += v * g_Xall[c*96 + lane + 64];
    }
    g_AX[r*96 + lane]      = a0;
    g_AX[r*96 + lane + 32] = a1;
    g_AX[r*96 + lane + 64] = a2;
}

// merged: W fragment build + bias/WX prep (block 0)
// frag layout within layer: (((ks*32 + nt)*2 + b)*2 + hl)*32 + lane
// k = ks*16 + b*8 + 2*tig (+1), n = nt*8 + g  (lane = g*4 + tig)
__global__ void wfragbias_kernel(
    const float* __restrict__ gcWh0, const float* __restrict__ liWh0,
    const float* __restrict__ gcWi1, const float* __restrict__ liWi1,
    const float* __restrict__ gcWh1, const float* __restrict__ liWh1,
    const float* __restrict__ gcWi0, const float* __restrict__ liWi0,
    const float* __restrict__ gcbi0, const float* __restrict__ gcbh0,
    const float* __restrict__ libi0, const float* __restrict__ libh0,
    const float* __restrict__ gcbi1, const float* __restrict__ gcbh1,
    const float* __restrict__ libi1, const float* __restrict__ libh1)
{
    const int idx = blockIdx.x * 256 + threadIdx.x;    // < 98304
    if (idx < 98304) {
        const int L = (idx >= 32768);
        const int j = L ? idx - 32768 : idx;
        const int lane = j & 31, hl = (j >> 5) & 1, b = (j >> 6) & 1;
        const int nt = (j >> 7) & 31, ks = j >> 12;
        const int g = lane >> 2, tig = lane & 3;
        const int k0 = ks*16 + b*8 + 2*tig;
        const int n  = nt*8 + g;
        unsigned short h2[2];
        #pragma unroll
        for (int e = 0; e < 2; e++) {
            const int k = k0 + e;
            const float* src;
            if (!L) src = (k < 64) ? (gcWh0 + k*256) : (liWh0 + (k-64)*256);
            else {
                const int q = k >> 6;
                src = (q == 0) ? (gcWi1 + k*256)
                    : (q == 1) ? (liWi1 + (k-64)*256)
                    : (q == 2) ? (gcWh1 + (k-128)*256)
                               : (liWh1 + (k-192)*256);
            }
            const float w = src[n];
            __nv_bfloat16 bh = __float2bfloat16(w);
            if (hl) bh = __float2bfloat16(w - __bfloat162float(bh));
            h2[e] = __bfloat16_as_ushort(bh);
        }
        const unsigned val = (unsigned)h2[0] | ((unsigned)h2[1] << 16);
        if (L) g_Wf1[j] = val; else g_Wf0[j] = val;
    }
    if (blockIdx.x == 0) {
        const int c = threadIdx.x;   // 256
        g_b0[c] = gcbi0[c] + gcbh0[c] + libi0[c] + libh0[c];
        g_b1[c] = gcbi1[c] + gcbh1[c] + libi1[c] + libh1[c];
        g_WX[c]       = gcWi0[c];
        g_WX[256 + c] = gcWi0[256 + c];
        g_WX[512 + c] = liWi0[c];
        g_WX[768 + c] = liWi0[256 + c];
    }
}

// ---------------- fused cell kernel (tensor-core GEMM) ----------------
// 16-row tiles, grid 256, 256 threads (~2 CTAs/SM).
// Phase 1: cp.async-prefetch first W chunks; stage h + SpMM gather (vectorized:
//   float2 h-loads, int4/float4 index loads) -> bf16 hi/lo smem slots.
// Phase 2: comb = src @ Wcat via mma.sync bf16 x3 split; W staged in 16KB
//   ks-chunks through a 2-deep cp.async ring (fully overlapped).
// Phase 3: LSTM gates.
template<int LAYER>
__global__ void __launch_bounds__(256, 2) cell_kernel(int pi, int t)
{
    constexpr int NSRC  = (LAYER == 0) ? 1 : 2;
    constexpr int SLOTS = 2*NSRC;
    constexpr int NCH   = SLOTS*4;               // 16KB W chunks
    constexpr int HALF  = 16*72;                 // bf16 elems per slot-half
    constexpr int SRC_BYTES = SLOTS*2*HALF*2;
    extern __shared__ char smem[];
    __nv_bfloat16* s_src = (__nv_bfloat16*)smem;              // [slot*2+hl][16*72]
    unsigned*      s_w   = (unsigned*)(smem + SRC_BYTES);     // 2 x 4096 u32 ring
    float*         s_comb= (float*)(smem + SRC_BYTES + 32768);// 16*256 f32

    const int po = pi ^ 1;
    const float* __restrict__ hA   = (LAYER == 0) ? (g_h0 + pi*SZH) : (g_h0 + po*SZH);
    const float* __restrict__ hB   = g_h1 + pi*SZH;
    float*       __restrict__ hout = (LAYER == 0) ? (g_h0 + po*SZH) : (g_h1 + po*SZH);
    float*       __restrict__ cst  = (LAYER == 0) ? g_c0 : g_c1;
    const float* __restrict__ btot = (LAYER == 0) ? g_b0 : g_b1;
    const unsigned* __restrict__ WF = (LAYER == 0) ? g_Wf0 : g_Wf1;
    const float2* __restrict__ hA2 = (const float2*)hA;
    const float2* __restrict__ hB2 = (const float2*)hB;

    const int tid = threadIdx.x, lane = tid & 31, warp = tid >> 5;
    const int r0 = blockIdx.x * 16;

    auto issue_chunk = [&](int c) {
        const float4* gsrc = (const float4*)(WF + c*4096);
        float4* dst = (float4*)(s_w + (c & 1)*4096);
        #pragma unroll
        for (int i = 0; i < 4; i++)
            cp_async16(dst + tid + i*256, gsrc + tid + i*256);
        cp_commit();
    };
    issue_chunk(0);
    issue_chunk(1);

    // ---- stage h slots (slot 1 = hA; slot 3 = hB) as bf16 hi/lo pairs ----
    for (int i = tid; i < 512; i += 256) {
        const int n = i >> 5, l2 = i & 31;
        store_hilo(s_src + (1*2+0)*HALF, s_src + (1*2+1)*HALF,
                   n*72 + 2*l2, hA2[(r0+n)*32 + l2]);
        if (NSRC == 2)
            store_hilo(s_src + (3*2+0)*HALF, s_src + (3*2+1)*HALF,
                       n*72 + 2*l2, hB2[(r0+n)*32 + l2]);
    }

    // ---- SpMM gather: Ah -> slot 0 (and slot 2); lane = col-pair 2l,2l+1 ----
    for (int rr = warp; rr < 16; rr += 8) {
        const int r = r0 + rr;
        const int cn = g_cnt[r];
        const int*   cp = g_cols + r*MAXNZ;
        const float* vp = g_vals + r*MAXNZ;
        float2 a0 = make_float2(0.f, 0.f), a1 = make_float2(0.f, 0.f);
        int k = 0;
        #pragma unroll 1
        for (; k + 4 <= cn; k += 4) {
            const int4   c4 = *(const int4*)(cp + k);
            const float4 v4 = *(const float4*)(vp + k);
            const float2 p0 = hA2[c4.x*32 + lane], p1 = hA2[c4.y*32 + lane];
            const float2 p2 = hA2[c4.z*32 + lane], p3 = hA2[c4.w*32 + lane];
            if (NSRC == 2) {
                const float2 q0 = hB2[c4.x*32 + lane], q1 = hB2[c4.y*32 + lane];
                const float2 q2 = hB2[c4.z*32 + lane], q3 = hB2[c4.w*32 + lane];
                a1.x += v4.x*q0.x + v4.y*q1.x + v4.z*q2.x + v4.w*q3.x;
                a1.y += v4.x*q0.y + v4.y*q1.y + v4.z*q2.y + v4.w*q3.y;
            }
            a0.x += v4.x*p0.x + v4.y*p1.x + v4.z*p2.x + v4.w*p3.x;
            a0.y += v4.x*p0.y + v4.y*p1.y + v4.z*p2.y + v4.w*p3.y;
        }
        for (; k < cn; k++) {
            const int c = cp[k]; const float v = vp[k];
            const float2 p = hA2[c*32 + lane];
            a0.x += v*p.x; a0.y += v*p.y;
            if (NSRC == 2) {
                const float2 q = hB2[c*32 + lane];
                a1.x += v*q.x; a1.y += v*q.y;
            }
        }
        store_hilo(s_src + 0*HALF, s_src + 1*HALF, rr*72 + 2*lane, a0);
        if (NSRC == 2)
            store_hilo(s_src + (2*2+0)*HALF, s_src + (2*2+1)*HALF, rr*72 + 2*lane, a1);
    }
    __syncthreads();   // gather/stage visible to all warps

    // ---- tensor-core GEMM over NCH chunks (2-deep cp.async ring) ----
    const int g = lane >> 2, tig = lane & 3;
    float acc[4][4];
    #pragma unroll
    for (int nt = 0; nt < 4; nt++) {
        const int col = (warp*4 + nt)*8 + 2*tig;
        const float b0v = btot[col], b1v = btot[col+1];
        acc[nt][0] = b0v; acc[nt][1] = b1v; acc[nt][2] = b0v; acc[nt][3] = b1v;
    }

    #pragma unroll
    for (int c = 0; c < NCH; c++) {
        if (c == NCH - 1) cp_wait<0>(); else cp_wait<1>();
        __syncthreads();                          // chunk c resident for all
        const int slot = c >> 2, ks = c & 3;
        const __nv_bfloat16* ah = s_src + (slot*2+0)*HALF;
        const __nv_bfloat16* al = s_src + (slot*2+1)*HALF;
        unsigned Ah[4], Al[4];
        const int ab = g*72 + ks*16 + 2*tig;
        Ah[0] = *(const unsigned*)(ah + ab);
        Ah[1] = *(const unsigned*)(ah + ab + 8*72);
        Ah[2] = *(const unsigned*)(ah + ab + 8);
        Ah[3] = *(const unsigned*)(ah + ab + 8*72 + 8);
        Al[0] = *(const unsigned*)(al + ab);
        Al[1] = *(const unsigned*)(al + ab + 8*72);
        Al[2] = *(const unsigned*)(al + ab + 8);
        Al[3] = *(const unsigned*)(al + ab + 8*72 + 8);
        const unsigned* wp = s_w + (c & 1)*4096 + warp*512 + lane;
        #pragma unroll
        for (int nt = 0; nt < 4; nt++) {
            const unsigned b0h = wp[nt*128];
            const unsigned b1h = wp[nt*128 + 64];
            const unsigned b0l = wp[nt*128 + 32];
            const unsigned b1l = wp[nt*128 + 96];
            MMA_BF16(acc[nt], Ah, b0h, b1h);
            MMA_BF16(acc[nt], Ah, b0l, b1l);
            MMA_BF16(acc[nt], Al, b0h, b1h);
        }
        __syncthreads();                          // chunk c reads done
        if (c + 2 < NCH) issue_chunk(c + 2);      // safe: ring slot free
    }

    if (LAYER == 0) {   // rank-2 x terms in fp32: (A x_t)@gcWi0 + x_t@liWi0
        const int rA = r0 + g, rB = rA + 8;
        float sA[4], sB[4];
        sA[0] = g_AX  [rA*96 + 2*t]; sA[1] = g_AX  [rA*96 + 2*t + 1];
        sA[2] = g_Xall[rA*96 + 2*t]; sA[3] = g_Xall[rA*96 + 2*t + 1];
        sB[0] = g_AX  [rB*96 + 2*t]; sB[1] = g_AX  [rB*96 + 2*t + 1];
        sB[2] = g_Xall[rB*96 + 2*t]; sB[3] = g_Xall[rB*96 + 2*t + 1];
        #pragma unroll
        for (int nt = 0; nt < 4; nt++) {
            const int col = (warp*4 + nt)*8 + 2*tig;
            #pragma unroll
            for (int jx = 0; jx < 4; jx++) {
                const float w0 = g_WX[jx*256 + col], w1 = g_WX[jx*256 + col + 1];
                acc[nt][0] += sA[jx]*w0; acc[nt][1] += sA[jx]*w1;
                acc[nt][2] += sB[jx]*w0; acc[nt][3] += sB[jx]*w1;
            }
        }
    }

    // ---- write comb to smem, then gates ----
    #pragma unroll
    for (int nt = 0; nt < 4; nt++) {
        const int col = (warp*4 + nt)*8 + 2*tig;
        *(float2*)(s_comb + g*256 + col)       = make_float2(acc[nt][0], acc[nt][1]);
        *(float2*)(s_comb + (g + 8)*256 + col) = make_float2(acc[nt][2], acc[nt][3]);
    }
    __syncthreads();
    for (int i = tid; i < 1024; i += 256) {
        const int n = i >> 6, hc = i & 63;
        const float ig = s_comb[n*256 + hc];
        const float fg = s_comb[n*256 + 64  + hc];
        const float og = s_comb[n*256 + 128 + hc];
        const float gg = s_comb[n*256 + 192 + hc];
        const int gi = (r0 + n)*64 + hc;
        const float cold = cst[gi];
        const float cnew = sigf(fg)*cold + sigf(ig)*tanhf(gg);
        cst[gi]  = cnew;
        hout[gi] = sigf(og)*tanhf(cnew);
    }
}

// out[n,p] = h1_final[n,:] @ outW + outb
__global__ void outproj_kernel(const float* __restrict__ outW,
                               const float* __restrict__ outb,
                               float* __restrict__ out) {
    const int idx = blockIdx.x*blockDim.x + threadIdx.x;
    if (idx >= NN*12) return;
    const int n = idx / 12, p = idx - n*12;
    const float* h = g_h1 + n*64;    // final ping index 0 after t=47
    float s = outb[p];
    #pragma unroll
    for (int k = 0; k < 64; k++) s += h[k] * outW[k*12 + p];
    out[idx] = s;
}

// ---------------- launch ----------------
extern "C" void kernel_launch(void* const* d_in, const int* in_sizes, int n_in,
                              void* d_out, int out_size) {
    (void)in_sizes; (void)n_in; (void)out_size;
    const float* x     = (const float*)d_in[0];
    const float* adj   = (const float*)d_in[1];
    const float* gcWi0 = (const float*)d_in[2];
    const float* gcbi0 = (const float*)d_in[3];
    const float* gcWh0 = (const float*)d_in[4];
    const float* gcbh0 = (const float*)d_in[5];
    const float* liWi0 = (const float*)d_in[6];
    const float* libi0 = (const float*)d_in[7];
    const float* liWh0 = (const float*)d_in[8];
    const float* libh0 = (const float*)d_in[9];
    const float* gcWi1 = (const float*)d_in[10];
    const float* gcbi1 = (const float*)d_in[11];
    const float* gcWh1 = (const float*)d_in[12];
    const float* gcbh1 = (const float*)d_in[13];
    const float* liWi1 = (const float*)d_in[14];
    const float* libi1 = (const float*)d_in[15];
    const float* liWh1 = (const float*)d_in[16];
    const float* libh1 = (const float*)d_in[17];
    const float* outW  = (const float*)d_in[18];
    const float* outb  = (const float*)d_in[19];
    float* out = (float*)d_out;

    const int SMEM0 = 2*2*16*72*2 + 32768 + 16384;   // 58368
    const int SMEM1 = 4*2*16*72*2 + 32768 + 16384;   // 67584
    cudaFuncSetAttribute(cell_kernel<0>, cudaFuncAttributeMaxDynamicSharedMemorySize, SMEM0);
    cudaFuncSetAttribute(cell_kernel<1>, cudaFuncAttributeMaxDynamicSharedMemorySize, SMEM1);

    // 5 setup launches, so ncu (-s 5 -c 1) profiles the first cell_kernel<0>.
    deg_kernel     <<<NN, 256>>>(adj);
    ell_kernel     <<<NN/8, 256>>>(adj);
    xallzero_kernel<<<(NN*96)/256, 256>>>(x);
    spmm96_kernel  <<<NN/8, 256>>>();
    wfragbias_kernel<<<384, 256>>>(gcWh0, liWh0, gcWi1, liWi1, gcWh1, liWh1,
                                   gcWi0, liWi0,
                                   gcbi0, gcbh0, libi0, libh0,
                                   gcbi1, gcbh1, libi1, libh1);

    for (int t = 0; t < TT; t++) {
        const int pi = t & 1;
        cell_kernel<0><<<NN/16, 256, SMEM0>>>(pi, t);
        cell_kernel<1><<<NN/16, 256, SMEM1>>>(pi, t);
    }
    outproj_kernel<<<(NN*12 + 255)/256, 256>>>(outW, outb, out);
}